// round 5
// baseline (speedup 1.0000x reference)
#include <cuda_runtime.h>
#include <cuda_bf16.h>
#include <cstdint>

// ===================== problem constants =====================
#define BDIM 8192
#define DDIM 512
#define BM 128
#define BN 128
#define BK 128         // fp8 per K-chunk = 128 bytes/row (one SW128 atom row)
#define NK (DDIM / BK) // 4
#define NSTAGE 3
#define FP8_SCALE 16.0f        // inputs scaled by 16 before e4m3 quantization
#define FP8_INV_SS (1.0f / 256.0f)

#define SMEM_STAGE_BYTES (2 * BM * 128)              // A 16KB + B 16KB = 32KB
#define SMEM_BYTES (NSTAGE * SMEM_STAGE_BYTES)       // 98304

// ===================== device scratch =====================
__device__ uint8_t g_vn8[(size_t)BDIM * DDIM];   // e4m3, x16 scale
__device__ uint8_t g_tn8[(size_t)BDIM * DDIM];
__device__ float g_sum;
__device__ int g_done;

// ===================== helpers =====================
__device__ __forceinline__ uint32_t smem_u32(const void* p) {
    uint32_t a;
    asm("{ .reg .u64 t; cvta.to.shared.u64 t, %1; cvt.u32.u64 %0, t; }" : "=r"(a) : "l"(p));
    return a;
}

#define SWZ128(off) ((off) ^ (((off) >> 3) & 0x70))

__device__ __forceinline__ void cp_async16(uint32_t saddr, const void* gptr) {
    asm volatile("cp.async.cg.shared.global [%0], [%1], 16;\n" :: "r"(saddr), "l"(gptr) : "memory");
}
__device__ __forceinline__ void cp_commit() {
    asm volatile("cp.async.commit_group;\n" ::: "memory");
}
template <int N>
__device__ __forceinline__ void cp_wait() {
    asm volatile("cp.async.wait_group %0;\n" :: "n"(N) : "memory");
}

__device__ __forceinline__ void ldsm_x4(uint32_t& r0, uint32_t& r1, uint32_t& r2, uint32_t& r3,
                                        uint32_t addr) {
    asm volatile("ldmatrix.sync.aligned.m8n8.x4.shared.b16 {%0,%1,%2,%3}, [%4];"
                 : "=r"(r0), "=r"(r1), "=r"(r2), "=r"(r3) : "r"(addr));
}

// fp8 e4m3 MMA: m16n8k32, fragments byte-compatible with the bf16 16816 ldmatrix path
__device__ __forceinline__ void mma16832_e4m3(float* d, const uint32_t* a, const uint32_t* b) {
    asm volatile(
        "mma.sync.aligned.m16n8k32.row.col.f32.e4m3.e4m3.f32 "
        "{%0,%1,%2,%3}, {%4,%5,%6,%7}, {%8,%9}, {%0,%1,%2,%3};"
        : "+f"(d[0]), "+f"(d[1]), "+f"(d[2]), "+f"(d[3])
        : "r"(a[0]), "r"(a[1]), "r"(a[2]), "r"(a[3]), "r"(b[0]), "r"(b[1]));
}

// pack 4 floats -> 4 e4m3 bytes (byte0=a .. byte3=d); cvt puts FIRST src in HIGH byte
__device__ __forceinline__ uint32_t pack_e4m3_4(float a, float b, float c, float d) {
    uint16_t lo, hi;
    asm("cvt.rn.satfinite.e4m3x2.f32 %0, %1, %2;" : "=h"(lo) : "f"(b), "f"(a));
    asm("cvt.rn.satfinite.e4m3x2.f32 %0, %1, %2;" : "=h"(hi) : "f"(d), "f"(c));
    return (uint32_t)lo | ((uint32_t)hi << 16);
}

// ===================== kernel A: L2-normalize rows -> e4m3 (x16) =====================
__global__ void __launch_bounds__(256) norm_kernel(const float* __restrict__ v,
                                                   const float* __restrict__ t) {
    int wid = threadIdx.x >> 5, lane = threadIdx.x & 31;
    int row = blockIdx.x * 8 + wid;   // 2048 blocks * 8 warps = 16384 rows
    const float* src;
    uint8_t* dst;
    if (row < BDIM) {
        src = v + (size_t)row * DDIM;
        dst = g_vn8 + (size_t)row * DDIM;
    } else {
        int r2 = row - BDIM;
        src = t + (size_t)r2 * DDIM;
        dst = g_tn8 + (size_t)r2 * DDIM;
    }
    float4 a[4];
    float ss = 0.0f;
#pragma unroll
    for (int i = 0; i < 4; i++) {
        a[i] = reinterpret_cast<const float4*>(src)[lane + i * 32];
        ss += a[i].x * a[i].x + a[i].y * a[i].y + a[i].z * a[i].z + a[i].w * a[i].w;
    }
#pragma unroll
    for (int o = 16; o; o >>= 1) ss += __shfl_xor_sync(0xffffffffu, ss, o);
    float sc = FP8_SCALE / fmaxf(sqrtf(ss), 1e-12f);
    // each lane writes 16 contiguous bytes (4 groups of 4 elems) at byte offset lane*16
    uint4 pk;
    pk.x = pack_e4m3_4(a[0].x * sc, a[0].y * sc, a[0].z * sc, a[0].w * sc);
    pk.y = pack_e4m3_4(a[1].x * sc, a[1].y * sc, a[1].z * sc, a[1].w * sc);
    pk.z = pack_e4m3_4(a[2].x * sc, a[2].y * sc, a[2].z * sc, a[2].w * sc);
    pk.w = pack_e4m3_4(a[3].x * sc, a[3].y * sc, a[3].z * sc, a[3].w * sc);
    // element i*32+lane*... careful: lane owns elems {lane+0*32..} interleaved; instead write
    // to the matching positions: group g (i) covers elems (lane + i*32)*... they are float4
    // loads at index lane+i*32 -> elems 4*(lane+i*32).. so byte offset 4*(lane+i*32)
    reinterpret_cast<uint32_t*>(dst)[lane + 0 * 32] = pk.x;
    reinterpret_cast<uint32_t*>(dst)[lane + 1 * 32] = pk.y;
    reinterpret_cast<uint32_t*>(dst)[lane + 2 * 32] = pk.z;
    reinterpret_cast<uint32_t*>(dst)[lane + 3 * 32] = pk.w;
    if (blockIdx.x == 0 && threadIdx.x == 0) { g_sum = 0.0f; g_done = 0; }
}

// ===================== kernel B: fp8 mma.sync GEMM + fused BCE + finalize =====================
__device__ __forceinline__ void load_chunk(const uint8_t* Ag, const uint8_t* Bg,
                                           int kk, uint32_t stageBase, int tid) {
    const uint8_t* gA = Ag + kk * BK;         // byte offset; row stride 512 B
    const uint8_t* gB = Bg + kk * BK;
#pragma unroll
    for (int i = 0; i < 4; i++) {
        int c = tid + i * 256;          // 1024 16B-chunks : 128 rows x 8 segs
        int row = c >> 3, seg = c & 7;
        uint32_t off = (uint32_t)(row * 128 + seg * 16);
        cp_async16(stageBase + SWZ128(off), gA + (size_t)row * DDIM + seg * 16);
    }
#pragma unroll
    for (int i = 0; i < 4; i++) {
        int c = tid + i * 256;
        int row = c >> 3, seg = c & 7;
        uint32_t off = (uint32_t)(row * 128 + seg * 16);
        cp_async16(stageBase + 16384 + SWZ128(off), gB + (size_t)row * DDIM + seg * 16);
    }
    cp_commit();
}

__global__ void __launch_bounds__(256, 2) gemm_bce_kernel(const float* __restrict__ log_temp,
                                                          const float* __restrict__ bias,
                                                          float* __restrict__ out) {
    extern __shared__ char smem[];
    uint32_t sbase = smem_u32(smem);
    int tid = threadIdx.x;
    int wid = tid >> 5, lane = tid & 31;
    int warp_m = wid >> 1, warp_n = wid & 1;   // 4 x 2 warp grid: 32 rows x 64 cols each

    // supertile swizzle: 8 tm-tiles per group for L2 locality
    int linear = blockIdx.x;                   // 0..4095
    int super = linear >> 9;                   // /512
    int rem = linear & 511;
    int tm = (super << 3) | (rem & 7);
    int tn = rem >> 3;

    const uint8_t* Ag = g_vn8 + (size_t)tm * BM * DDIM;
    const uint8_t* Bg = g_tn8 + (size_t)tn * BN * DDIM;

    float acc[2][8][4];
#pragma unroll
    for (int i = 0; i < 2; i++)
#pragma unroll
        for (int j = 0; j < 8; j++)
#pragma unroll
            for (int e = 0; e < 4; e++) acc[i][j][e] = 0.0f;

    // Swizzled ldmatrix base addresses; per k-step XOR kx in {0,32,64,96} (bits 5-6,
    // disjoint from the swizzle's source bits 7-9 -> XOR trick stays exact).
    uint32_t aC[2];
#pragma unroll
    for (int mt = 0; mt < 2; mt++) {
        int row = warp_m * 32 + mt * 16 + (lane & 15);
        uint32_t m = (uint32_t)((row & 7) * 16);
        uint32_t hi = (uint32_t)((lane >> 4) * 16);
        aC[mt] = (uint32_t)(row * 128) + ((hi ^ m) & 0x10u) + (m & 0x60u);
    }
    uint32_t bC[4];
#pragma unroll
    for (int np = 0; np < 4; np++) {
        int n = warp_n * 64 + np * 16 + (lane & 7) + ((lane >> 4) * 8);
        uint32_t m = (uint32_t)((n & 7) * 16);
        uint32_t hi = (uint32_t)(((lane >> 3) & 1) * 16);
        bC[np] = (uint32_t)(n * 128) + ((hi ^ m) & 0x10u) + (m & 0x60u) + 16384u;
    }

    // prologue: prefetch chunks 0,1
    load_chunk(Ag, Bg, 0, sbase + 0 * SMEM_STAGE_BYTES, tid);
    load_chunk(Ag, Bg, 1, sbase + 1 * SMEM_STAGE_BYTES, tid);

    int s = 0, ps = 2;
#pragma unroll 1
    for (int k = 0; k < NK; k++) {
        if (k + 1 < NK) cp_wait<1>(); else cp_wait<0>();
        __syncthreads();

        if (k + 2 < NK)
            load_chunk(Ag, Bg, k + 2, sbase + (uint32_t)ps * SMEM_STAGE_BYTES, tid);

        uint32_t stage = sbase + (uint32_t)s * SMEM_STAGE_BYTES;
#pragma unroll
        for (int ks = 0; ks < 4; ks++) {
            uint32_t kx = (uint32_t)(ks * 32);     // 32 bytes = 32 fp8 k-elems per step
            uint32_t a[2][4];
#pragma unroll
            for (int mt = 0; mt < 2; mt++)
                ldsm_x4(a[mt][0], a[mt][1], a[mt][2], a[mt][3], stage + (aC[mt] ^ kx));
#pragma unroll
            for (int np = 0; np < 4; np++) {
                uint32_t b[4];
                ldsm_x4(b[0], b[1], b[2], b[3], stage + (bC[np] ^ kx));
#pragma unroll
                for (int mt = 0; mt < 2; mt++) {
                    mma16832_e4m3(acc[mt][np * 2 + 0], a[mt], &b[0]);
                    mma16832_e4m3(acc[mt][np * 2 + 1], a[mt], &b[2]);
                }
            }
        }

        s = (s == NSTAGE - 1) ? 0 : s + 1;
        ps = (ps == NSTAGE - 1) ? 0 : ps + 1;
    }

    // -------- fused BCE epilogue --------
    // acc holds (16*v)·(16*t) = 256*sim ; fold 1/256 into inv_temp
    float inv_temp = __expf(-(*log_temp)) * FP8_INV_SS;
    float bval = *bias;
    float lsum = 0.0f;
    int row0 = tm * BM + warp_m * 32 + (lane >> 2);
    int col0 = tn * BN + warp_n * 64 + (lane & 3) * 2;

#pragma unroll
    for (int mt = 0; mt < 2; mt++) {
#pragma unroll
        for (int nt = 0; nt < 8; nt++) {
#pragma unroll
            for (int e = 0; e < 4; e++) {
                float z = fmaf(acc[mt][nt][e], inv_temp, bval);   // z in [-25.4, 5.4]: no clamp needed
                float x = __expf(-fabsf(z));
                float p = x * (1.0f - x * (0.5f - 0.33333333f * x));  // log1p(x), x small
                float bce = fmaxf(z, 0.0f) + p;
                int row = row0 + mt * 16 + (e >> 1) * 8;
                int col = col0 + nt * 8 + (e & 1);
                if (row == col) bce -= z;   // diagonal positive label
                lsum += bce;
            }
        }
    }
#pragma unroll
    for (int o = 16; o; o >>= 1) lsum += __shfl_xor_sync(0xffffffffu, lsum, o);

    // block reduction -> single atomicAdd per CTA (pipeline smem is dead now)
    float* red = reinterpret_cast<float*>(smem);
    __syncthreads();
    if (lane == 0) red[wid] = lsum;
    __syncthreads();
    if (tid == 0) {
        float sblk = 0.0f;
#pragma unroll
        for (int i = 0; i < 8; i++) sblk += red[i];
        atomicAdd(&g_sum, sblk);
        __threadfence();
        int ticket = atomicAdd(&g_done, 1);
        if (ticket == 4095) {
            float tot = atomicAdd(&g_sum, 0.0f);   // coherent read of final value
            out[0] = tot * (1.0f / ((float)BDIM * (float)BDIM));
        }
    }
}

// ===================== launch =====================
extern "C" void kernel_launch(void* const* d_in, const int* in_sizes, int n_in,
                              void* d_out, int out_size) {
    const float* v = (const float*)d_in[0];
    const float* t = (const float*)d_in[1];
    const float* log_temp = (const float*)d_in[2];
    const float* bias = (const float*)d_in[3];
    float* out = (float*)d_out;

    norm_kernel<<<2 * BDIM / 8, 256>>>(v, t);

    cudaFuncSetAttribute(gemm_bce_kernel, cudaFuncAttributeMaxDynamicSharedMemorySize, SMEM_BYTES);
    gemm_bce_kernel<<<4096, 256, SMEM_BYTES>>>(log_temp, bias, out);
}

// round 6
// speedup vs baseline: 1.0511x; 1.0511x over previous
#include <cuda_runtime.h>
#include <cuda_bf16.h>
#include <cstdint>

// ===================== problem constants =====================
#define BDIM 8192
#define DDIM 512
#define BM 128
#define BN 128
#define BK 64          // bf16 per K-chunk = 128 bytes/row (one SW128 atom row)
#define NK (DDIM / BK) // 8
#define NSTAGE 3
#define TILES_M (BDIM / BM)        // 64
#define TILES_N (BDIM / BN)        // 64
#define TOTAL_TILES (TILES_M * TILES_N)  // 4096
#define NCTA 296                   // 2 per SM * 148 SMs

#define SMEM_STAGE_BYTES (2 * BM * 128)              // A 16KB + B 16KB = 32KB
#define SMEM_PIPE_BYTES (NSTAGE * SMEM_STAGE_BYTES)  // 98304
#define SMEM_BYTES (SMEM_PIPE_BYTES + 128)           // + reduction scratch

// ===================== device scratch =====================
__device__ __nv_bfloat16 g_vn[(size_t)BDIM * DDIM];
__device__ __nv_bfloat16 g_tn[(size_t)BDIM * DDIM];
__device__ float g_sum;
__device__ int g_done;

// ===================== helpers =====================
__device__ __forceinline__ uint32_t smem_u32(const void* p) {
    uint32_t a;
    asm("{ .reg .u64 t; cvta.to.shared.u64 t, %1; cvt.u32.u64 %0, t; }" : "=r"(a) : "l"(p));
    return a;
}

#define SWZ128(off) ((off) ^ (((off) >> 3) & 0x70))

__device__ __forceinline__ void cp_async16(uint32_t saddr, const void* gptr) {
    asm volatile("cp.async.cg.shared.global [%0], [%1], 16;\n" :: "r"(saddr), "l"(gptr) : "memory");
}
__device__ __forceinline__ void cp_commit() {
    asm volatile("cp.async.commit_group;\n" ::: "memory");
}
template <int N>
__device__ __forceinline__ void cp_wait() {
    asm volatile("cp.async.wait_group %0;\n" :: "n"(N) : "memory");
}

__device__ __forceinline__ void ldsm_x4(uint32_t& r0, uint32_t& r1, uint32_t& r2, uint32_t& r3,
                                        uint32_t addr) {
    asm volatile("ldmatrix.sync.aligned.m8n8.x4.shared.b16 {%0,%1,%2,%3}, [%4];"
                 : "=r"(r0), "=r"(r1), "=r"(r2), "=r"(r3) : "r"(addr));
}

__device__ __forceinline__ void mma16816(float* d, const uint32_t* a, const uint32_t* b) {
    asm volatile(
        "mma.sync.aligned.m16n8k16.row.col.f32.bf16.bf16.f32 "
        "{%0,%1,%2,%3}, {%4,%5,%6,%7}, {%8,%9}, {%0,%1,%2,%3};"
        : "+f"(d[0]), "+f"(d[1]), "+f"(d[2]), "+f"(d[3])
        : "r"(a[0]), "r"(a[1]), "r"(a[2]), "r"(a[3]), "r"(b[0]), "r"(b[1]));
}

// ===================== kernel A: L2-normalize rows (warp per row) =====================
__global__ void __launch_bounds__(256) norm_kernel(const float* __restrict__ v,
                                                   const float* __restrict__ t) {
    int wid = threadIdx.x >> 5, lane = threadIdx.x & 31;
    int row = blockIdx.x * 8 + wid;   // 2048 blocks * 8 warps = 16384 rows
    const float* src;
    __nv_bfloat16* dst;
    if (row < BDIM) {
        src = v + (size_t)row * DDIM;
        dst = g_vn + (size_t)row * DDIM;
    } else {
        int r2 = row - BDIM;
        src = t + (size_t)r2 * DDIM;
        dst = g_tn + (size_t)r2 * DDIM;
    }
    float4 a[4];
    float ss = 0.0f;
#pragma unroll
    for (int i = 0; i < 4; i++) {
        a[i] = reinterpret_cast<const float4*>(src)[lane + i * 32];
        ss += a[i].x * a[i].x + a[i].y * a[i].y + a[i].z * a[i].z + a[i].w * a[i].w;
    }
#pragma unroll
    for (int o = 16; o; o >>= 1) ss += __shfl_xor_sync(0xffffffffu, ss, o);
    float sc = 1.0f / fmaxf(sqrtf(ss), 1e-12f);
#pragma unroll
    for (int i = 0; i < 4; i++) {
        __nv_bfloat162 lo = __floats2bfloat162_rn(a[i].x * sc, a[i].y * sc);
        __nv_bfloat162 hi = __floats2bfloat162_rn(a[i].z * sc, a[i].w * sc);
        uint2 pk = make_uint2(*(uint32_t*)&lo, *(uint32_t*)&hi);
        reinterpret_cast<uint2*>(dst)[lane + i * 32] = pk;
    }
    if (blockIdx.x == 0 && threadIdx.x == 0) { g_sum = 0.0f; g_done = 0; }
}

// ===================== kernel B: persistent mma.sync GEMM + fused BCE =====================
// global chunk index c -> tile = ctaid + (c>>3)*NCTA ; tm = tile>>6 ; tn = tile&63 ; kk = c&7
__device__ __forceinline__ void load_chunk_g(int ctaid, int c, uint32_t stageBase, int tid) {
    int tile = ctaid + (c >> 3) * NCTA;
    int tm = tile >> 6, tn = tile & 63;
    int kk = c & 7;
    const __nv_bfloat16* gA = g_vn + (size_t)tm * BM * DDIM + kk * BK;
    const __nv_bfloat16* gB = g_tn + (size_t)tn * BN * DDIM + kk * BK;
#pragma unroll
    for (int i = 0; i < 4; i++) {
        int cc = tid + i * 256;          // 1024 16B-chunks : 128 rows x 8 segs
        int row = cc >> 3, seg = cc & 7;
        uint32_t off = (uint32_t)(row * 128 + seg * 16);
        cp_async16(stageBase + SWZ128(off), gA + (size_t)row * DDIM + seg * 8);
    }
#pragma unroll
    for (int i = 0; i < 4; i++) {
        int cc = tid + i * 256;
        int row = cc >> 3, seg = cc & 7;
        uint32_t off = (uint32_t)(row * 128 + seg * 16);
        cp_async16(stageBase + 16384 + SWZ128(off), gB + (size_t)row * DDIM + seg * 8);
    }
    cp_commit();
}

__global__ void __launch_bounds__(256, 2) gemm_bce_kernel(const float* __restrict__ log_temp,
                                                          const float* __restrict__ bias,
                                                          float* __restrict__ out) {
    extern __shared__ char smem[];
    uint32_t sbase = smem_u32(smem);
    int tid = threadIdx.x;
    int wid = tid >> 5, lane = tid & 31;
    int warp_m = wid >> 1, warp_n = wid & 1;   // 4 x 2 warp grid: 32 rows x 64 cols each
    int ctaid = blockIdx.x;

    int n_tiles = (TOTAL_TILES - ctaid + NCTA - 1) / NCTA;   // 13 or 14
    int total = n_tiles * NK;

    float acc[2][8][4];
#pragma unroll
    for (int i = 0; i < 2; i++)
#pragma unroll
        for (int j = 0; j < 8; j++)
#pragma unroll
            for (int e = 0; e < 4; e++) acc[i][j][e] = 0.0f;

    // Swizzled ldmatrix base addresses (verified R2 layout); per ks XOR kx in {0,32,64,96}.
    uint32_t aC[2];
#pragma unroll
    for (int mt = 0; mt < 2; mt++) {
        int row = warp_m * 32 + mt * 16 + (lane & 15);
        uint32_t m = (uint32_t)((row & 7) * 16);
        uint32_t hi = (uint32_t)((lane >> 4) * 16);
        aC[mt] = (uint32_t)(row * 128) + ((hi ^ m) & 0x10u) + (m & 0x60u);
    }
    uint32_t bC[4];
#pragma unroll
    for (int np = 0; np < 4; np++) {
        int n = warp_n * 64 + np * 16 + (lane & 7) + ((lane >> 4) * 8);
        uint32_t m = (uint32_t)((n & 7) * 16);
        uint32_t hi = (uint32_t)(((lane >> 3) & 1) * 16);
        bC[np] = (uint32_t)(n * 128) + ((hi ^ m) & 0x10u) + (m & 0x60u) + 16384u;
    }

    float inv_temp = __expf(-(*log_temp));
    float bval = *bias;
    float lsum = 0.0f;
    // warp-local base offsets within a tile (for diag detection)
    int wr0 = warp_m * 32 + (lane >> 2);
    int wc0 = warp_n * 64 + (lane & 3) * 2;

    // prologue: prefetch chunks 0,1 (pipeline never drains until the very end)
    load_chunk_g(ctaid, 0, sbase + 0 * SMEM_STAGE_BYTES, tid);
    load_chunk_g(ctaid, 1, sbase + 1 * SMEM_STAGE_BYTES, tid);

    int s = 0, ps = 2;
#pragma unroll 1
    for (int c = 0; c < total; c++) {
        if (c + 1 < total) cp_wait<1>(); else cp_wait<0>();
        __syncthreads();

        if (c + 2 < total)
            load_chunk_g(ctaid, c + 2, sbase + (uint32_t)ps * SMEM_STAGE_BYTES, tid);

        uint32_t stage = sbase + (uint32_t)s * SMEM_STAGE_BYTES;
#pragma unroll
        for (int ks = 0; ks < 4; ks++) {
            uint32_t kx = (uint32_t)(ks * 32);
            uint32_t a[2][4];
#pragma unroll
            for (int mt = 0; mt < 2; mt++)
                ldsm_x4(a[mt][0], a[mt][1], a[mt][2], a[mt][3], stage + (aC[mt] ^ kx));
#pragma unroll
            for (int np = 0; np < 4; np++) {
                uint32_t b[4];
                ldsm_x4(b[0], b[1], b[2], b[3], stage + (bC[np] ^ kx));
#pragma unroll
                for (int mt = 0; mt < 2; mt++) {
                    mma16816(acc[mt][np * 2 + 0], a[mt], &b[0]);
                    mma16816(acc[mt][np * 2 + 1], a[mt], &b[2]);
                }
            }
        }

        if ((c & (NK - 1)) == NK - 1) {
            // -------- per-tile BCE epilogue (registers only; loads for next tile in flight) --------
            int tile = ctaid + (c >> 3) * NCTA;
            int tm = tile >> 6, tn = tile & 63;
            int row0 = tm * BM + wr0;
            int col0 = tn * BN + wc0;
#pragma unroll
            for (int mt = 0; mt < 2; mt++) {
#pragma unroll
                for (int nt = 0; nt < 8; nt++) {
#pragma unroll
                    for (int e = 0; e < 4; e++) {
                        float z = fminf(fmaxf(fmaf(acc[mt][nt][e], inv_temp, bval), -30.0f), 30.0f);
                        float x = __expf(-fabsf(z));
                        float p = x * (1.0f - x * (0.5f - 0.33333333f * x));  // log1p(x), x small
                        float bce = fmaxf(z, 0.0f) + p;
                        int row = row0 + mt * 16 + (e >> 1) * 8;
                        int col = col0 + nt * 8 + (e & 1);
                        if (row == col) bce -= z;   // diagonal positive label
                        lsum += bce;
                        acc[mt][nt][e] = 0.0f;      // reset for next tile
                    }
                }
            }
        }

        s = (s == NSTAGE - 1) ? 0 : s + 1;
        ps = (ps == NSTAGE - 1) ? 0 : ps + 1;
    }

    // -------- final reduction: one atomicAdd per CTA --------
#pragma unroll
    for (int o = 16; o; o >>= 1) lsum += __shfl_xor_sync(0xffffffffu, lsum, o);
    float* red = reinterpret_cast<float*>(smem + SMEM_PIPE_BYTES);
    __syncthreads();
    if (lane == 0) red[wid] = lsum;
    __syncthreads();
    if (tid == 0) {
        float sblk = 0.0f;
#pragma unroll
        for (int i = 0; i < 8; i++) sblk += red[i];
        atomicAdd(&g_sum, sblk);
        __threadfence();
        int ticket = atomicAdd(&g_done, 1);
        if (ticket == NCTA - 1) {
            float tot = atomicAdd(&g_sum, 0.0f);   // coherent read of final value
            out[0] = tot * (1.0f / ((float)BDIM * (float)BDIM));
        }
    }
}

// ===================== launch =====================
extern "C" void kernel_launch(void* const* d_in, const int* in_sizes, int n_in,
                              void* d_out, int out_size) {
    const float* v = (const float*)d_in[0];
    const float* t = (const float*)d_in[1];
    const float* log_temp = (const float*)d_in[2];
    const float* bias = (const float*)d_in[3];
    float* out = (float*)d_out;

    norm_kernel<<<2 * BDIM / 8, 256>>>(v, t);

    cudaFuncSetAttribute(gemm_bce_kernel, cudaFuncAttributeMaxDynamicSharedMemorySize, SMEM_BYTES);
    gemm_bce_kernel<<<NCTA, 256, SMEM_BYTES>>>(log_temp, bias, out);
}